// round 1
// baseline (speedup 1.0000x reference)
#include <cuda_runtime.h>

// ---------------------------------------------------------------------------
// Net_40312563041045: 4-layer max-tempered MLP
//   layer(x; W, b) = 0.8 * (W @ x) + 0.2 * max_i(W[o,i]*x[b,i]) + b
// Shapes: x[1024,256], W1[512,256], W2/W3[512,512], W4[1,512] -> out[1024]
// ---------------------------------------------------------------------------

#define BMp 68   // padded smem row stride (floats): 16B-aligned, breaks store conflicts

__device__ __align__(16) float g_buf0[1024 * 512];
__device__ __align__(16) float g_buf1[1024 * 512];

// One block computes a 64x64 output tile. 256 threads, 4x4 register tile each.
// Double-buffered smem tiles, K-major-transposed for conflict-free LDS.128.
__global__ __launch_bounds__(256, 1) void tempered_layer(
    const float* __restrict__ X,     // [M, K]
    const float* __restrict__ Wm,    // [N, K]
    const float* __restrict__ bias,  // [N]
    float* __restrict__ Y,           // [M, N]
    int K, int N)
{
    __shared__ __align__(16) float xs[2][16 * BMp];
    __shared__ __align__(16) float ws[2][16 * BMp];

    const int tid  = threadIdx.x;
    const int tx   = tid & 15;        // N-dim thread coord (0..15)
    const int ty   = tid >> 4;        // M-dim thread coord (0..15)
    const int row0 = blockIdx.x * 64;
    const int col0 = blockIdx.y * 64;

    // tile-load mapping: each thread loads one float4 along K
    const int lm  = tid >> 2;         // 0..63 (row within tile)
    const int lk4 = (tid & 3) << 2;   // 0,4,8,12 (k offset)

    const float* Xp = X  + (size_t)(row0 + lm) * K + lk4;
    const float* Wp = Wm + (size_t)(col0 + lm) * K + lk4;

    float4 xr = *(const float4*)Xp;
    float4 wr = *(const float4*)Wp;

    float acc[4][4], mx[4][4];
#pragma unroll
    for (int i = 0; i < 4; ++i)
#pragma unroll
        for (int j = 0; j < 4; ++j) {
            acc[i][j] = 0.0f;
            mx[i][j]  = -3.402823466e38f;
        }

    const int T = K >> 4;

    // store tile 0 into buffer 0 (transposed: xs[k][m])
    {
        float* xd = &xs[0][lk4 * BMp + lm];
        float* wd = &ws[0][lk4 * BMp + lm];
        xd[0] = xr.x; xd[BMp] = xr.y; xd[2 * BMp] = xr.z; xd[3 * BMp] = xr.w;
        wd[0] = wr.x; wd[BMp] = wr.y; wd[2 * BMp] = wr.z; wd[3 * BMp] = wr.w;
    }
    __syncthreads();

    for (int t = 0; t < T; ++t) {
        // prefetch next tile global -> regs (latency hidden under compute)
        if (t + 1 < T) {
            xr = *(const float4*)(Xp + (t + 1) * 16);
            wr = *(const float4*)(Wp + (t + 1) * 16);
        }

        const float* xb = xs[t & 1];
        const float* wb = ws[t & 1];
#pragma unroll
        for (int k = 0; k < 16; ++k) {
            float4 xv = *(const float4*)(xb + k * BMp + 4 * ty);
            float4 wv = *(const float4*)(wb + k * BMp + 4 * tx);
            float xa[4] = {xv.x, xv.y, xv.z, xv.w};
            float wa[4] = {wv.x, wv.y, wv.z, wv.w};
#pragma unroll
            for (int i = 0; i < 4; ++i)
#pragma unroll
                for (int j = 0; j < 4; ++j) {
                    float p = xa[i] * wa[j];
                    acc[i][j] += p;
                    mx[i][j] = fmaxf(mx[i][j], p);
                }
        }

        // stage next tile regs -> other smem buffer
        if (t + 1 < T) {
            float* xd = &xs[(t + 1) & 1][lk4 * BMp + lm];
            float* wd = &ws[(t + 1) & 1][lk4 * BMp + lm];
            xd[0] = xr.x; xd[BMp] = xr.y; xd[2 * BMp] = xr.z; xd[3 * BMp] = xr.w;
            wd[0] = wr.x; wd[BMp] = wr.y; wd[2 * BMp] = wr.z; wd[3 * BMp] = wr.w;
        }
        __syncthreads();
    }

    // epilogue: out = 0.8*lin + 0.2*max + bias
    const int cbase = col0 + 4 * tx;
    float4 bv = *(const float4*)(bias + cbase);
    float ba[4] = {bv.x, bv.y, bv.z, bv.w};
#pragma unroll
    for (int i = 0; i < 4; ++i) {
        const int r = row0 + 4 * ty + i;
        float4 o;
        o.x = 0.8f * acc[i][0] + 0.2f * mx[i][0] + ba[0];
        o.y = 0.8f * acc[i][1] + 0.2f * mx[i][1] + ba[1];
        o.z = 0.8f * acc[i][2] + 0.2f * mx[i][2] + ba[2];
        o.w = 0.8f * acc[i][3] + 0.2f * mx[i][3] + ba[3];
        *(float4*)(Y + (size_t)r * N + cbase) = o;
    }
}

// Final layer: OUT=1. One warp per batch row, warp-reduce sum & max.
__global__ __launch_bounds__(256) void out_layer(
    const float* __restrict__ H,   // [B, K]
    const float* __restrict__ w4,  // [K]
    const float* __restrict__ b4,  // [1]
    float* __restrict__ out,       // [B]
    int K)
{
    const int warp = (blockIdx.x * blockDim.x + threadIdx.x) >> 5;
    const int lane = threadIdx.x & 31;

    const float* h = H + (size_t)warp * K;
    float s = 0.0f;
    float m = -3.402823466e38f;
    for (int i = lane; i < K; i += 32) {
        float p = w4[i] * h[i];
        s += p;
        m = fmaxf(m, p);
    }
#pragma unroll
    for (int o = 16; o > 0; o >>= 1) {
        s += __shfl_xor_sync(0xFFFFFFFFu, s, o);
        m = fmaxf(m, __shfl_xor_sync(0xFFFFFFFFu, m, o));
    }
    if (lane == 0) out[warp] = 0.8f * s + 0.2f * m + b4[0];
}

extern "C" void kernel_launch(void* const* d_in, const int* in_sizes, int n_in,
                              void* d_out, int out_size)
{
    const float* x  = (const float*)d_in[0];
    const float* W1 = (const float*)d_in[1];
    const float* b1 = (const float*)d_in[2];
    const float* W2 = (const float*)d_in[3];
    const float* b2 = (const float*)d_in[4];
    const float* W3 = (const float*)d_in[5];
    const float* b3 = (const float*)d_in[6];
    const float* W4 = (const float*)d_in[7];
    const float* b4 = (const float*)d_in[8];

    const int Wd = in_sizes[2];            // hidden width = 512
    const int IN = in_sizes[1] / Wd;       // 256
    const int B  = in_sizes[0] / IN;       // 1024

    float *h0, *h1;
    cudaGetSymbolAddress((void**)&h0, g_buf0);
    cudaGetSymbolAddress((void**)&h1, g_buf1);

    dim3 grid(B / 64, Wd / 64);
    tempered_layer<<<grid, 256>>>(x,  W1, b1, h0, IN, Wd);   // h1 = L1(x)
    tempered_layer<<<grid, 256>>>(h0, W2, b2, h1, Wd, Wd);   // h2 = L2(h1)
    tempered_layer<<<grid, 256>>>(h1, W3, b3, h0, Wd, Wd);   // h3 = L3(h2)
    out_layer<<<B / 8, 256>>>(h0, W4, b4, (float*)d_out, Wd); // out = L4(h3)
}

// round 2
// speedup vs baseline: 1.0538x; 1.0538x over previous
#include <cuda_runtime.h>

// ---------------------------------------------------------------------------
// Net_40312563041045: 4-layer max-tempered MLP
//   layer(x; W, b) = 0.8 * (W @ x) + 0.2 * max_i(W[o,i]*x[b,i]) + b
// f32x2-packed inner loop: 2 products per fma-pipe instruction.
// ---------------------------------------------------------------------------

#define SPITCH 132   // smem row stride in floats for each kp row (128 data + 4 pad)

__device__ __align__(16) float g_buf0[1024 * 512];
__device__ __align__(16) float g_buf1[1024 * 512];

union F4U2 { float4 f4; unsigned long long u[2]; };

__device__ __forceinline__ unsigned long long mul2(unsigned long long a, unsigned long long b) {
    unsigned long long d;
    asm("mul.rn.f32x2 %0, %1, %2;" : "=l"(d) : "l"(a), "l"(b));
    return d;
}
__device__ __forceinline__ void add2(unsigned long long& acc, unsigned long long p) {
    asm("add.rn.f32x2 %0, %0, %1;" : "+l"(acc) : "l"(p));
}
__device__ __forceinline__ void unpack2(unsigned long long p, float& lo, float& hi) {
    asm("mov.b64 {%0, %1}, %2;" : "=f"(lo), "=f"(hi) : "l"(p));
}

// 64x64 output tile per block, 256 threads, 4x4 register tile (K-pair packed).
// Smem layout per BK=16 tile: 8 kp-rows of 128 floats: [kp][m*2 + (k&1)].
__global__ __launch_bounds__(256, 1) void tempered_layer(
    const float* __restrict__ X,     // [M, K]
    const float* __restrict__ Wm,    // [N, K]
    const float* __restrict__ bias,  // [N]
    float* __restrict__ Y,           // [M, N]
    int K, int N)
{
    __shared__ __align__(16) float xs[2][8 * SPITCH];
    __shared__ __align__(16) float ws[2][8 * SPITCH];

    const int tid  = threadIdx.x;
    const int lane = tid & 31;
    const int wrp  = tid >> 5;
    // conflict-free compute mapping: within a phase (8 lanes) tx spans 4
    // distinct values (32B apart -> distinct bank groups), ty spans 2.
    const int tx = (lane & 3) | ((wrp & 3) << 2);          // 0..15 (N dim)
    const int ty = ((lane >> 2) & 7) | ((wrp >> 2) << 3);  // 0..15 (M dim)

    const int row0 = blockIdx.x * 64;
    const int col0 = blockIdx.y * 64;

    // tile-load mapping: each thread loads one float4 along K
    const int lm  = tid >> 2;         // 0..63 (row within tile)
    const int lk4 = (tid & 3) << 2;   // 0,4,8,12
    const int kp0 = lk4 >> 1;         // 0,2,4,6

    const float* Xp = X  + (size_t)(row0 + lm) * K + lk4;
    const float* Wp = Wm + (size_t)(col0 + lm) * K + lk4;

    float4 xr = *(const float4*)Xp;
    float4 wr = *(const float4*)Wp;

    unsigned long long acc[4][4];
    float mxlo[4][4], mxhi[4][4];
#pragma unroll
    for (int i = 0; i < 4; ++i)
#pragma unroll
        for (int j = 0; j < 4; ++j) {
            acc[i][j]  = 0ull;                      // (0.0f, 0.0f)
            mxlo[i][j] = -3.402823466e38f;
            mxhi[i][j] = -3.402823466e38f;
        }

    const int T = K >> 4;

    // stage tile 0 (interleaved k-pairs: row kp holds k-even at m*2, k-odd at m*2+1)
    {
        float* xd = &xs[0][kp0 * SPITCH + lm * 2];
        float* wd = &ws[0][kp0 * SPITCH + lm * 2];
        *(float2*)xd            = make_float2(xr.x, xr.y);
        *(float2*)(xd + SPITCH) = make_float2(xr.z, xr.w);
        *(float2*)wd            = make_float2(wr.x, wr.y);
        *(float2*)(wd + SPITCH) = make_float2(wr.z, wr.w);
    }
    __syncthreads();

    for (int t = 0; t < T; ++t) {
        if (t + 1 < T) {
            xr = *(const float4*)(Xp + (t + 1) * 16);
            wr = *(const float4*)(Wp + (t + 1) * 16);
        }

        const float* xb = xs[t & 1];
        const float* wb = ws[t & 1];
#pragma unroll
        for (int kp = 0; kp < 8; ++kp) {
            F4U2 xa0, xa1, wa0, wa1;
            xa0.f4 = *(const float4*)(xb + kp * SPITCH + 8 * ty);
            xa1.f4 = *(const float4*)(xb + kp * SPITCH + 8 * ty + 4);
            wa0.f4 = *(const float4*)(wb + kp * SPITCH + 8 * tx);
            wa1.f4 = *(const float4*)(wb + kp * SPITCH + 8 * tx + 4);
            unsigned long long x2[4] = {xa0.u[0], xa0.u[1], xa1.u[0], xa1.u[1]};
            unsigned long long w2[4] = {wa0.u[0], wa0.u[1], wa1.u[0], wa1.u[1]};
#pragma unroll
            for (int i = 0; i < 4; ++i)
#pragma unroll
                for (int j = 0; j < 4; ++j) {
                    unsigned long long p = mul2(x2[i], w2[j]);
                    add2(acc[i][j], p);
                    float plo, phi;
                    unpack2(p, plo, phi);
                    mxlo[i][j] = fmaxf(mxlo[i][j], plo);
                    mxhi[i][j] = fmaxf(mxhi[i][j], phi);
                }
        }

        if (t + 1 < T) {
            float* xd = &xs[(t + 1) & 1][kp0 * SPITCH + lm * 2];
            float* wd = &ws[(t + 1) & 1][kp0 * SPITCH + lm * 2];
            *(float2*)xd            = make_float2(xr.x, xr.y);
            *(float2*)(xd + SPITCH) = make_float2(xr.z, xr.w);
            *(float2*)wd            = make_float2(wr.x, wr.y);
            *(float2*)(wd + SPITCH) = make_float2(wr.z, wr.w);
        }
        __syncthreads();
    }

    // epilogue: out = 0.8*(acc_lo+acc_hi) + 0.2*max(mxlo,mxhi) + bias
    const int cbase = col0 + 4 * tx;
    float4 bv = *(const float4*)(bias + cbase);
    float ba[4] = {bv.x, bv.y, bv.z, bv.w};
#pragma unroll
    for (int i = 0; i < 4; ++i) {
        const int r = row0 + 4 * ty + i;
        float o[4];
#pragma unroll
        for (int j = 0; j < 4; ++j) {
            float alo, ahi;
            unpack2(acc[i][j], alo, ahi);
            float lin = alo + ahi;
            float mx  = fmaxf(mxlo[i][j], mxhi[i][j]);
            o[j] = 0.8f * lin + 0.2f * mx + ba[j];
        }
        *(float4*)(Y + (size_t)r * N + cbase) = make_float4(o[0], o[1], o[2], o[3]);
    }
}

// Final layer: OUT=1. One warp per batch row, float4 loads, warp-reduce.
__global__ __launch_bounds__(256) void out_layer(
    const float* __restrict__ H,   // [B, K]
    const float* __restrict__ w4,  // [K]
    const float* __restrict__ b4,  // [1]
    float* __restrict__ out,       // [B]
    int K)
{
    const int warp = (blockIdx.x * blockDim.x + threadIdx.x) >> 5;
    const int lane = threadIdx.x & 31;

    const float4* h4 = (const float4*)(H + (size_t)warp * K);
    const float4* w44 = (const float4*)w4;
    const int K4 = K >> 2;

    float s = 0.0f;
    float m = -3.402823466e38f;
    for (int i = lane; i < K4; i += 32) {
        float4 hv = h4[i];
        float4 wv = w44[i];
        float p0 = wv.x * hv.x, p1 = wv.y * hv.y, p2 = wv.z * hv.z, p3 = wv.w * hv.w;
        s += (p0 + p1) + (p2 + p3);
        m = fmaxf(m, fmaxf(fmaxf(p0, p1), fmaxf(p2, p3)));
    }
#pragma unroll
    for (int o = 16; o > 0; o >>= 1) {
        s += __shfl_xor_sync(0xFFFFFFFFu, s, o);
        m = fmaxf(m, __shfl_xor_sync(0xFFFFFFFFu, m, o));
    }
    if (lane == 0) out[warp] = 0.8f * s + 0.2f * m + b4[0];
}

extern "C" void kernel_launch(void* const* d_in, const int* in_sizes, int n_in,
                              void* d_out, int out_size)
{
    const float* x  = (const float*)d_in[0];
    const float* W1 = (const float*)d_in[1];
    const float* b1 = (const float*)d_in[2];
    const float* W2 = (const float*)d_in[3];
    const float* b2 = (const float*)d_in[4];
    const float* W3 = (const float*)d_in[5];
    const float* b3 = (const float*)d_in[6];
    const float* W4 = (const float*)d_in[7];
    const float* b4 = (const float*)d_in[8];

    const int Wd = in_sizes[2];            // hidden width = 512
    const int IN = in_sizes[1] / Wd;       // 256
    const int B  = in_sizes[0] / IN;       // 1024

    float *h0, *h1;
    cudaGetSymbolAddress((void**)&h0, g_buf0);
    cudaGetSymbolAddress((void**)&h1, g_buf1);

    dim3 grid(B / 64, Wd / 64);
    tempered_layer<<<grid, 256>>>(x,  W1, b1, h0, IN, Wd);
    tempered_layer<<<grid, 256>>>(h0, W2, b2, h1, Wd, Wd);
    tempered_layer<<<grid, 256>>>(h1, W3, b3, h0, Wd, Wd);
    out_layer<<<B / 8, 256>>>(h0, W4, b4, (float*)d_out, Wd);
}